// round 6
// baseline (speedup 1.0000x reference)
#include <cuda_runtime.h>
#include <cstdint>

#define BATCH 32
#define CH    256
#define HH    56
#define WW    56
#define HW    (HH*WW)
#define NELEM (BATCH*CH*HW)
#define EPSBN 1e-5f

// padded act layout: [b][row' 0..57][slot 0..63][c 0..255] s8 (+1/-1, pad 0)
#define SLOTS 64
#define PROWS 58
#define PPB   (PROWS*SLOTS)        // 3712
#define ABST  (PPB*CH)             // 950272 bytes per batch
#define GUARD 4096
#define NPIXP (BATCH*PPB)          // 118784

__device__ __align__(16) float   g_y[NELEM];
__device__ __align__(16) uint8_t g_act1[GUARD + BATCH*ABST + GUARD];
__device__ __align__(16) uint8_t g_act2[GUARD + BATCH*ABST + GUARD];
__device__ __align__(16) uint8_t g_Bw[2][2][9][2][128][128];   // [blk][nhalf][tap][chalf][o][c] s8 +-1
__device__ float g_k1[2][CH], g_k2[2][CH], g_c0[2][CH];

// ---------------- helpers ----------------
__device__ __forceinline__ uint32_t smem_u32(const void* p) {
    uint32_t a;
    asm("{ .reg .u64 t; cvta.to.shared.u64 t, %1; cvt.u32.u64 %0, t; }" : "=r"(a) : "l"(p));
    return a;
}
__device__ __forceinline__ void cpa16(uint32_t dst, const void* src) {
    asm volatile("cp.async.cg.shared.global [%0], [%1], 16;" :: "r"(dst), "l"(src));
}
#define CP_COMMIT() asm volatile("cp.async.commit_group;" ::: "memory")
#define CP_WAIT1()  asm volatile("cp.async.wait_group 1;" ::: "memory")
#define CP_WAIT0()  asm volatile("cp.async.wait_group 0;" ::: "memory")

__device__ __forceinline__ void ldsm4(uint32_t* r, uint32_t addr) {
    asm volatile("ldmatrix.sync.aligned.m8n8.x4.shared.b16 {%0,%1,%2,%3}, [%4];"
        : "=r"(r[0]), "=r"(r[1]), "=r"(r[2]), "=r"(r[3]) : "r"(addr));
}
__device__ __forceinline__ void mma_s8(int* c, const uint32_t* a, uint32_t b0, uint32_t b1) {
    asm volatile("mma.sync.aligned.m16n8k32.row.col.s32.s8.s8.s32 "
        "{%0,%1,%2,%3}, {%4,%5,%6,%7}, {%8,%9}, {%0,%1,%2,%3};"
        : "+r"(c[0]), "+r"(c[1]), "+r"(c[2]), "+r"(c[3])
        : "r"(a[0]), "r"(a[1]), "r"(a[2]), "r"(a[3]), "r"(b0), "r"(b1));
}

// ---------------- prep: weights -> s8 +-1 tiles + fused epilogue coeffs ----------------
__global__ void prep_kernel(const float* __restrict__ w, const float* __restrict__ sc,
                            const float* __restrict__ g, const float* __restrict__ beta,
                            const float* __restrict__ mean, const float* __restrict__ var, int blk)
{
    const int o = blockIdx.x, tid = threadIdx.x;   // 128 threads
    __shared__ float red[128];
    float s = 0.f;
    const float* wo = w + o * (CH * 9);
    for (int i = tid; i < CH * 9; i += 128) s += fabsf(wo[i]);
    red[tid] = s;
    __syncthreads();
    for (int st = 64; st > 0; st >>= 1) { if (tid < st) red[tid] += red[tid + st]; __syncthreads(); }

    for (int ch = 0; ch < 2; ch++) {
        const int c = ch * 128 + tid;
        for (int tap = 0; tap < 9; tap++) {
            const float wv = w[(o * CH + c) * 9 + tap];
            g_Bw[blk][o >> 7][tap][ch][o & 127][tid] = (wv > 0.f) ? 0x01 : 0xFF;
        }
    }
    if (tid == 0) {
        const float alpha = red[0] / (float)(CH * 9);
        const float istd  = rsqrtf(var[o] + EPSBN);
        const float k1 = alpha * istd * g[o];
        g_k1[blk][o] = k1;
        g_k2[blk][o] = sc[o] * k1;
        g_c0[blk][o] = beta[o] - mean[o] * istd * g[o];
    }
}

// ---------------- pack: NCHW float -> padded s8 [b][row'][slot][c] ----------------
__global__ void pack_kernel(const float* __restrict__ in,
                            const float* __restrict__ shA, const float* __restrict__ shB)
{
    __shared__ float s1[CH], s2[CH];
    const int tid = threadIdx.x;                 // 256
    s1[tid] = shA[tid]; s2[tid] = shB[tid];
    __syncthreads();

    const int pix = blockIdx.x * 256 + tid;      // 0..NPIXP-1
    const int b = pix / PPB, rem = pix % PPB;
    const int rr = rem / SLOTS, ss = rem % SLOTS;
    uint4* o1 = (uint4*)(g_act1 + GUARD + (size_t)pix * CH);
    uint4* o2 = (uint4*)(g_act2 + GUARD + (size_t)pix * CH);

    if (rr >= 1 && rr <= HH && ss >= 1 && ss <= WW) {
        const size_t base = (size_t)b * CH * HW + (size_t)(rr - 1) * WW + (ss - 1);
        #pragma unroll
        for (int g16 = 0; g16 < 16; g16++) {
            uint32_t q1[4], q2[4];
            #pragma unroll
            for (int q = 0; q < 4; q++) {
                uint32_t a = 0, bb = 0;
                #pragma unroll
                for (int k = 0; k < 4; k++) {
                    const int c = g16 * 16 + q * 4 + k;
                    const float v = in[base + (size_t)c * HW];
                    a  |= ((v + s1[c] > 0.f) ? 0x01u : 0xFFu) << (k * 8);
                    bb |= ((v + s2[c] > 0.f) ? 0x01u : 0xFFu) << (k * 8);
                }
                q1[q] = a; q2[q] = bb;
            }
            o1[g16] = make_uint4(q1[0], q1[1], q1[2], q1[3]);
            o2[g16] = make_uint4(q2[0], q2[1], q2[2], q2[3]);
        }
    } else {
        const uint4 z = make_uint4(0, 0, 0, 0);
        #pragma unroll
        for (int g16 = 0; g16 < 16; g16++) { o1[g16] = z; o2[g16] = z; }
    }
}

// ---------------- conv: implicit GEMM via mma.sync s8 ----------------
// CTA: 512 thr (16 warps), tile M=128 pixels x N=128 o, K=2304 (18 chunks of 128).
// smem: double buffer, each 48KB = A1(16K) + A2(16K) + B(16K), rows 128B swizzled.
#define BUFSZ   49152
#define SMEMTOT (2*BUFSZ)
#define NCHUNK  18

__global__ void __launch_bounds__(512, 1)
conv_kernel(int blk, const float* __restrict__ res, float* __restrict__ out)
{
    extern __shared__ __align__(16) uint8_t dsm[];
    const uint32_t sb = smem_u32(dsm);
    const int tid = threadIdx.x, warp = tid >> 5, lane = tid & 31;
    const int rp = blockIdx.x, b = blockIdx.y, nh = blockIdx.z;
    const int oBase = nh * 128;

    // ---- copy-unit precompute: 6 x 16B per thread per chunk (3072 units) ----
    int u_buf[6]; uint32_t u_dst[6], u_src[6];
    #pragma unroll
    for (int i = 0; i < 6; i++) {
        const int idx = i * 512 + tid;
        const int buf = idx >> 10;          // 0=A1, 1=A2, 2=B
        const int rem = idx & 1023;
        const int r = rem >> 3, seg = rem & 7;
        u_buf[i] = buf;
        u_dst[i] = (uint32_t)(buf * 16384 + r * 128 + ((seg * 16) ^ ((r & 7) << 4)));
        u_src[i] = (buf < 2) ? (uint32_t)(r * 256 + seg * 16) : (uint32_t)(r * 128 + seg * 16);
    }
    const uint8_t* a1g = g_act1 + GUARD + (size_t)b * ABST;
    const uint8_t* a2g = g_act2 + GUARD + (size_t)b * ABST;
    const uint8_t* bwg = &g_Bw[blk][nh][0][0][0][0];

    // ---- warp tiling ----
    const int mrow = warp >> 2, ncol = warp & 3;
    const int m0 = mrow * 32, n0 = ncol * 32;
    const int lr   = ((lane >> 3) & 1) * 8 + (lane & 7);   // row within 16-row frag
    const int csel = (lane >> 4) * 16;                     // 16B column select

    int acc[2][2][4][4];
    #pragma unroll
    for (int a = 0; a < 2; a++)
        #pragma unroll
        for (int mi = 0; mi < 2; mi++)
            #pragma unroll
            for (int ni = 0; ni < 4; ni++)
                #pragma unroll
                for (int k = 0; k < 4; k++) acc[a][mi][ni][k] = 0;

    // ---- issue chunk t into buffer t&1 ----
    auto issue = [&](int t) {
        const int tap = t >> 1, ch = t & 1;
        const int dh = tap / 3, dw = tap % 3;
        const long pixoff = ((long)((2 * rp + dh) * 64 + dw - 1)) * 256 + ch * 128;
        const size_t boff = (size_t)(tap * 2 + ch) * 16384;
        const uint32_t dstb = sb + (uint32_t)(t & 1) * BUFSZ;
        #pragma unroll
        for (int i = 0; i < 6; i++) {
            const uint8_t* src;
            if (u_buf[i] == 0)      src = a1g + pixoff + u_src[i];
            else if (u_buf[i] == 1) src = a2g + pixoff + u_src[i];
            else                    src = bwg + boff + u_src[i];
            cpa16(dstb + u_dst[i], src);
        }
        CP_COMMIT();
    };

    issue(0);

    for (int t = 0; t < NCHUNK; t++) {
        if (t < NCHUNK - 1) { issue(t + 1); CP_WAIT1(); }
        else                { CP_WAIT0(); }
        __syncthreads();

        const uint32_t bufb = sb + (uint32_t)(t & 1) * BUFSZ;
        #pragma unroll
        for (int kk = 0; kk < 4; kk++) {
            // B frags: two x4 loads cover n32 x k32
            uint32_t bfr[8];
            #pragma unroll
            for (int half = 0; half < 2; half++) {
                const int rB = n0 + half * 16 + lr;
                const uint32_t addr = bufb + 32768 + (uint32_t)rB * 128
                                    + (uint32_t)((kk * 32 + csel) ^ ((rB & 7) << 4));
                ldsm4(&bfr[half * 4], addr);
            }
            #pragma unroll
            for (int act = 0; act < 2; act++) {
                uint32_t afr[2][4];
                #pragma unroll
                for (int mi = 0; mi < 2; mi++) {
                    const int rA = m0 + mi * 16 + lr;
                    const uint32_t addr = bufb + (uint32_t)act * 16384 + (uint32_t)rA * 128
                                        + (uint32_t)((kk * 32 + csel) ^ ((rA & 7) << 4));
                    ldsm4(afr[mi], addr);
                }
                #pragma unroll
                for (int mi = 0; mi < 2; mi++)
                    #pragma unroll
                    for (int ni = 0; ni < 4; ni++) {
                        const int base = (ni >> 1) * 4 + (ni & 1);
                        mma_s8(acc[act][mi][ni], afr[mi], bfr[base], bfr[base + 2]);
                    }
            }
        }
        __syncthreads();
    }

    // ---- epilogue: combine acts in regs, transpose via smem, coalesced store ----
    float* stage = (float*)dsm;                     // [128 o][132 m] floats
    const float* k1p = g_k1[blk];
    const float* k2p = g_k2[blk];
    const float* c0p = g_c0[blk];
    const int g = lane >> 2, q = lane & 3;

    #pragma unroll
    for (int mi = 0; mi < 2; mi++)
        #pragma unroll
        for (int ni = 0; ni < 4; ni++) {
            const int nb = n0 + (ni >> 1) * 16 + (ni & 1) * 8;   // frag n base
            const int ol0 = nb + 2 * q;
            const int o0 = oBase + ol0;
            const float k1a = __ldg(&k1p[o0]),     k2a = __ldg(&k2p[o0]),     c0a = __ldg(&c0p[o0]);
            const float k1b = __ldg(&k1p[o0 + 1]), k2b = __ldg(&k2p[o0 + 1]), c0b = __ldg(&c0p[o0 + 1]);
            const int mlo = m0 + mi * 16 + g, mhi = mlo + 8;
            const int* d1 = acc[0][mi][ni];
            const int* d2 = acc[1][mi][ni];
            stage[ol0 * 132 + mlo]       = k1a * (float)d1[0] + k2a * (float)d2[0] + c0a;
            stage[(ol0 + 1) * 132 + mlo] = k1b * (float)d1[1] + k2b * (float)d2[1] + c0b;
            stage[ol0 * 132 + mhi]       = k1a * (float)d1[2] + k2a * (float)d2[2] + c0a;
            stage[(ol0 + 1) * 132 + mhi] = k1b * (float)d1[3] + k2b * (float)d2[3] + c0b;
        }
    __syncthreads();

    #pragma unroll
    for (int rr = 0; rr < 8; rr++) {
        const int nloc = warp * 8 + rr;
        const int o = oBase + nloc;
        #pragma unroll
        for (int qq = 0; qq < 4; qq++) {
            const int m = qq * 32 + lane;
            const int slot = m & 63;
            const int hr = 2 * rp + (m >> 6);
            if (slot >= 1 && slot <= WW) {
                const size_t idx = ((size_t)(b * CH + o)) * HW + (size_t)hr * WW + (slot - 1);
                float v = stage[nloc * 132 + m] + res[idx];
                out[idx] = fminf(fmaxf(v, -1.0f), 1.0f);
            }
        }
    }
}

// ---------------- launch ----------------
extern "C" void kernel_launch(void* const* d_in, const int* in_sizes, int n_in,
                              void* d_out, int out_size)
{
    const float* x    = (const float*)d_in[0];
    const float* sh11 = (const float*)d_in[1];
    const float* sh12 = (const float*)d_in[2];
    const float* w1   = (const float*)d_in[3];
    const float* sc1  = (const float*)d_in[4];
    const float* g1   = (const float*)d_in[5];
    const float* b1   = (const float*)d_in[6];
    const float* m1   = (const float*)d_in[7];
    const float* v1   = (const float*)d_in[8];
    const float* sh21 = (const float*)d_in[9];
    const float* sh22 = (const float*)d_in[10];
    const float* w2   = (const float*)d_in[11];
    const float* sc2  = (const float*)d_in[12];
    const float* g2   = (const float*)d_in[13];
    const float* b2   = (const float*)d_in[14];
    const float* m2   = (const float*)d_in[15];
    const float* v2   = (const float*)d_in[16];
    float* outp = (float*)d_out;

    void* yp_raw = nullptr;
    cudaGetSymbolAddress(&yp_raw, g_y);
    float* yp = (float*)yp_raw;

    cudaFuncSetAttribute(conv_kernel, cudaFuncAttributeMaxDynamicSharedMemorySize, SMEMTOT);

    prep_kernel<<<CH, 128>>>(w1, sc1, g1, b1, m1, v1, 0);
    prep_kernel<<<CH, 128>>>(w2, sc2, g2, b2, m2, v2, 1);

    dim3 cgrid(28, BATCH, 2);   // 28 row-pairs x 32 batch x 2 o-halves

    pack_kernel<<<NPIXP / 256, 256>>>(x, sh11, sh12);
    conv_kernel<<<cgrid, 512, SMEMTOT>>>(0, x, yp);

    pack_kernel<<<NPIXP / 256, 256>>>(yp, sh21, sh22);
    conv_kernel<<<cgrid, 512, SMEMTOT>>>(1, yp, outp);
}

// round 7
// speedup vs baseline: 2.9113x; 2.9113x over previous
#include <cuda_runtime.h>
#include <cstdint>

// Problem constants
#define BATCH 32
#define CH    256
#define HH    56
#define WW    56
#define HW    (HH*WW)              // 3136
#define NPIX  (BATCH*HW)           // 100352
#define NELEM (BATCH*CH*HW)        // 25690112
#define NWORD 8
#define KTAPS 9
#define EPSBN 1e-5f

// Conv tiling
#define TH 8
#define TW 28
#define NTHREADS (TH*TW)           // 224
#define OSPLIT 4
#define OPB (CH/OSPLIT)            // 64
#define OG  4                      // o-channels per register group

// -------------------- device scratch --------------------
__device__ __align__(16) float    g_y[NELEM];
__device__ __align__(16) uint32_t g_abits1a[NPIX*NWORD];   // pack(x + sh11)
__device__ __align__(16) uint32_t g_abits2a[NPIX*NWORD];   // pack(x + sh12)
__device__ __align__(16) uint32_t g_abits1b[NPIX*NWORD];   // pack(y + sh21)  (written by conv1 epilogue)
__device__ __align__(16) uint32_t g_abits2b[NPIX*NWORD];   // pack(y + sh22)
__device__ __align__(16) uint32_t g_wbits[2][CH*KTAPS*NWORD];
__device__ int   g_popcw[2][CH*KTAPS];
__device__ float g_k1[2][CH], g_k2[2][CH], g_c0[2][CH];

// -------------------- prep (both sub-blocks in one launch) --------------------
__global__ void prep_kernel(const float* __restrict__ wA, const float* __restrict__ scA,
                            const float* __restrict__ gA, const float* __restrict__ betaA,
                            const float* __restrict__ meanA, const float* __restrict__ varA,
                            const float* __restrict__ wB, const float* __restrict__ scB,
                            const float* __restrict__ gB, const float* __restrict__ betaB,
                            const float* __restrict__ meanB, const float* __restrict__ varB)
{
    const int blk = blockIdx.y;
    const float* w    = blk ? wB : wA;
    const float* sc   = blk ? scB : scA;
    const float* g    = blk ? gB : gA;
    const float* beta = blk ? betaB : betaA;
    const float* mean = blk ? meanB : meanA;
    const float* var  = blk ? varB : varA;

    const int o = blockIdx.x, tid = threadIdx.x;   // 128 threads
    __shared__ float red[128];
    __shared__ int   tapc[KTAPS];

    float s = 0.f;
    const float* wo = w + o * (CH * KTAPS);
    for (int i = tid; i < CH * KTAPS; i += 128) s += fabsf(wo[i]);
    red[tid] = s;
    __syncthreads();
    for (int st = 64; st > 0; st >>= 1) {
        if (tid < st) red[tid] += red[tid + st];
        __syncthreads();
    }
    if (tid < KTAPS) tapc[tid] = 0;
    __syncthreads();

    if (tid < KTAPS * NWORD) {
        const int tap  = tid / NWORD;
        const int word = tid % NWORD;
        uint32_t bits = 0;
        #pragma unroll
        for (int j = 0; j < 32; j++) {
            const int c = word * 32 + j;
            const float wv = w[(o * CH + c) * KTAPS + tap];
            bits |= (uint32_t)(wv > 0.f) << j;
        }
        g_wbits[blk][(o * KTAPS + tap) * NWORD + word] = bits;
        atomicAdd(&tapc[tap], __popc(bits));
    }
    __syncthreads();
    if (tid < KTAPS) g_popcw[blk][o * KTAPS + tid] = tapc[tid];

    if (tid == 0) {
        const float alpha = red[0] / (float)(CH * KTAPS);
        const float istd  = rsqrtf(var[o] + EPSBN);
        const float k1 = alpha * istd * g[o];
        g_k1[blk][o] = k1;
        g_k2[blk][o] = sc[o] * k1;
        g_c0[blk][o] = beta[o] - mean[o] * istd * g[o];
    }
}

// -------------------- pack: float NCHW -> channel-packed sign bits --------------------
__global__ void pack_kernel(const float* __restrict__ in,
                            const float* __restrict__ shA, const float* __restrict__ shB,
                            uint32_t* __restrict__ ob1, uint32_t* __restrict__ ob2)
{
    __shared__ float s1[CH], s2[CH];
    const int tid = threadIdx.x;
    s1[tid] = shA[tid]; s2[tid] = shB[tid];
    __syncthreads();

    const int pix = blockIdx.x * blockDim.x + tid;
    if (pix >= NPIX) return;
    const int b  = pix / HW;
    const int hw = pix % HW;
    const int base = b * (CH * HW) + hw;

    #pragma unroll
    for (int k = 0; k < NWORD; k++) {
        uint32_t b1 = 0, b2 = 0;
        #pragma unroll
        for (int j = 0; j < 32; j++) {
            const int c = k * 32 + j;
            const float v = in[base + c * HW];
            b1 |= (uint32_t)(v + s1[c] > 0.f) << j;
            b2 |= (uint32_t)(v + s2[c] > 0.f) << j;
        }
        ob1[pix * NWORD + k] = b1;
        ob2[pix * NWORD + k] = b2;
    }
}

// -------------------- CSA popcount helpers --------------------
__device__ __forceinline__ void fa3(uint32_t a, uint32_t b, uint32_t c,
                                    uint32_t& s, uint32_t& cy) {
    s  = a ^ b ^ c;
    cy = (a & b) | (c & (a ^ b));
}

__device__ __forceinline__ int csa_popc8(uint32_t x0, uint32_t x1, uint32_t x2, uint32_t x3,
                                         uint32_t x4, uint32_t x5, uint32_t x6, uint32_t x7) {
    uint32_t s1a, c2a, s1b, c2b, s1c, c2c, s2, c4;
    fa3(x0, x1, x2, s1a, c2a);
    fa3(x3, x4, x5, s1b, c2b);
    fa3(s1a, s1b, x6, s1c, c2c);
    fa3(c2a, c2b, c2c, s2, c4);
    return __popc(s1c) + __popc(x7) + 2 * __popc(s2) + 4 * __popc(c4);
}

// -------------------- conv: XNOR + CSA, packed dual-act acc, optional fused re-pack --------------------
__global__ __launch_bounds__(NTHREADS, 4)
void conv_kernel(int blk,
                 const uint32_t* __restrict__ ab1, const uint32_t* __restrict__ ab2,
                 const float* __restrict__ residual, float* __restrict__ out,
                 int do_pack,
                 const float* __restrict__ shA2, const float* __restrict__ shB2)
{
    __shared__ __align__(16) uint32_t wsm[OPB * KTAPS * NWORD];   // 18KB
    __shared__ __align__(16) uint4    as4[2 * 10 * 2 * 30];       // 19.2KB

    const int tid    = threadIdx.x;
    const int colT   = blockIdx.x & 1;
    const int rowT   = blockIdx.x >> 1;
    const int b      = blockIdx.y;
    const int oBase  = blockIdx.z * OPB;
    const int h0     = rowT * TH;
    const int w0     = colT * TW;

    {
        const uint4* wsrc = reinterpret_cast<const uint4*>(&g_wbits[blk][oBase * KTAPS * NWORD]);
        uint4* wdst = reinterpret_cast<uint4*>(wsm);
        for (int i = tid; i < OPB * KTAPS * 2; i += NTHREADS) wdst[i] = wsrc[i];
    }
    {
        const uint4* s1g = reinterpret_cast<const uint4*>(ab1);
        const uint4* s2g = reinterpret_cast<const uint4*>(ab2);
        for (int idx = tid; idx < 2 * 300; idx += NTHREADS) {
            const int a    = idx / 300;
            const int cell = idx % 300;
            const int rr = cell / 30;
            const int cc = cell % 30;
            const int gh = h0 - 1 + rr;
            const int gw = w0 - 1 + cc;
            uint4 lo = make_uint4(0u, 0u, 0u, 0u);
            uint4 hi = make_uint4(0u, 0u, 0u, 0u);
            if (gh >= 0 && gh < HH && gw >= 0 && gw < WW) {
                const uint4* src = (a == 0) ? s1g : s2g;
                const int gidx = ((b * HH + gh) * WW + gw) * 2;
                lo = src[gidx];
                hi = src[gidx + 1];
            }
            const int dbase = a * 600 + rr * 60 + cc;
            as4[dbase]      = lo;
            as4[dbase + 30] = hi;
        }
    }
    __syncthreads();

    const int r = tid / TW;
    const int c = tid % TW;
    const int h = h0 + r;
    const int w = w0 + c;

    int oobmask = 0;
    #pragma unroll
    for (int tap = 0; tap < KTAPS; tap++) {
        const int dh = tap / 3 - 1, dw = tap % 3 - 1;
        if (h + dh < 0 || h + dh >= HH || w + dw < 0 || w + dw >= WW) oobmask |= 1 << tap;
    }

    const uint4* wsm4 = reinterpret_cast<const uint4*>(wsm);
    const float* k1p = g_k1[blk];
    const float* k2p = g_k2[blk];
    const float* c0p = g_c0[blk];
    const int*   pcw = g_popcw[blk];

    uint32_t pb[4] = {0, 0, 0, 0};   // fused re-pack words: [act1 lo, act1 hi, act2 lo, act2 hi]

    for (int og = 0; og < OPB / OG; og++) {       // 16 iterations x 4 o
        int acc[OG] = {0, 0, 0, 0};               // acc1 in low 16, acc2 in high 16

        #pragma unroll
        for (int dr = 0; dr < 3; dr++) {
            #pragma unroll
            for (int dc = 0; dc < 3; dc++) {
                const int tap = dr * 3 + dc;
                const int abx = (r + dr) * 60 + (c + dc);
                const uint4 a1l = as4[abx];
                const uint4 a1h = as4[abx + 30];
                const uint4 a2l = as4[abx + 600];
                const uint4 a2h = as4[abx + 630];
                #pragma unroll
                for (int j = 0; j < OG; j++) {
                    const int wi = ((og * OG + j) * KTAPS + tap) * 2;
                    const uint4 wl = wsm4[wi];
                    const uint4 wh = wsm4[wi + 1];
                    const int p1 = csa_popc8(a1l.x ^ wl.x, a1l.y ^ wl.y, a1l.z ^ wl.z, a1l.w ^ wl.w,
                                             a1h.x ^ wh.x, a1h.y ^ wh.y, a1h.z ^ wh.z, a1h.w ^ wh.w);
                    const int p2 = csa_popc8(a2l.x ^ wl.x, a2l.y ^ wl.y, a2l.z ^ wl.z, a2l.w ^ wl.w,
                                             a2h.x ^ wh.x, a2h.y ^ wh.y, a2h.z ^ wh.z, a2h.w ^ wh.w);
                    acc[j] = p2 * 65536 + (acc[j] + p1);   // IMAD on fma pipe
                }
            }
        }

        #pragma unroll
        for (int j = 0; j < OG; j++) {
            const int ol = og * OG + j;
            const int o  = oBase + ol;
            int corr = 0;
            if (oobmask) {
                #pragma unroll
                for (int tap = 0; tap < KTAPS; tap++)
                    if ((oobmask >> tap) & 1)
                        corr += CH - 2 * __ldg(&pcw[o * KTAPS + tap]);
            }
            const int a1 = acc[j] & 0xFFFF;
            const int a2 = acc[j] >> 16;
            const int d1 = CH * KTAPS - 2 * a1 - corr;
            const int d2 = CH * KTAPS - 2 * a2 - corr;
            const int oidx = ((b * CH + o) * HH + h) * WW + w;
            float val = __ldg(&k1p[o]) * (float)d1
                      + __ldg(&k2p[o]) * (float)d2
                      + __ldg(&c0p[o])
                      + residual[oidx];
            val = fminf(fmaxf(val, -1.0f), 1.0f);
            out[oidx] = val;

            if (do_pack) {   // emit sign(y + sh2x) bits for this o directly
                const uint32_t bit = 1u << (ol & 31);
                const int hi = ol >> 5;
                if (val + __ldg(&shA2[o]) > 0.f) pb[hi]     |= bit;
                if (val + __ldg(&shB2[o]) > 0.f) pb[2 + hi] |= bit;
            }
        }
    }

    if (do_pack) {
        const int gidx = ((b * HH + h) * WW + w) * NWORD + (oBase >> 5);
        g_abits1b[gidx]     = pb[0];
        g_abits1b[gidx + 1] = pb[1];
        g_abits2b[gidx]     = pb[2];
        g_abits2b[gidx + 1] = pb[3];
    }
}

// -------------------- launch --------------------
extern "C" void kernel_launch(void* const* d_in, const int* in_sizes, int n_in,
                              void* d_out, int out_size)
{
    const float* x    = (const float*)d_in[0];
    const float* sh11 = (const float*)d_in[1];
    const float* sh12 = (const float*)d_in[2];
    const float* w1   = (const float*)d_in[3];
    const float* sc1  = (const float*)d_in[4];
    const float* g1   = (const float*)d_in[5];
    const float* b1   = (const float*)d_in[6];
    const float* m1   = (const float*)d_in[7];
    const float* v1   = (const float*)d_in[8];
    const float* sh21 = (const float*)d_in[9];
    const float* sh22 = (const float*)d_in[10];
    const float* w2   = (const float*)d_in[11];
    const float* sc2  = (const float*)d_in[12];
    const float* g2   = (const float*)d_in[13];
    const float* b2   = (const float*)d_in[14];
    const float* m2   = (const float*)d_in[15];
    const float* v2   = (const float*)d_in[16];
    float* outp = (float*)d_out;

    void *yp_raw, *a1a, *a2a, *a1b, *a2b;
    cudaGetSymbolAddress(&yp_raw, g_y);
    cudaGetSymbolAddress(&a1a, g_abits1a);
    cudaGetSymbolAddress(&a2a, g_abits2a);
    cudaGetSymbolAddress(&a1b, g_abits1b);
    cudaGetSymbolAddress(&a2b, g_abits2b);
    float* yp = (float*)yp_raw;

    dim3 pgrid(CH, 2);
    prep_kernel<<<pgrid, 128>>>(w1, sc1, g1, b1, m1, v1,
                                w2, sc2, g2, b2, m2, v2);

    dim3 cgrid(14, BATCH, OSPLIT);

    // sub-block 1: pack(x), conv -> y, fused re-pack of y into *b arrays
    pack_kernel<<<(NPIX + 255) / 256, 256>>>(x, sh11, sh12, (uint32_t*)a1a, (uint32_t*)a2a);
    conv_kernel<<<cgrid, NTHREADS>>>(0, (const uint32_t*)a1a, (const uint32_t*)a2a,
                                     x, yp, 1, sh21, sh22);

    // sub-block 2: conv -> d_out (no pack needed)
    conv_kernel<<<cgrid, NTHREADS>>>(1, (const uint32_t*)a1b, (const uint32_t*)a2b,
                                     yp, outp, 0, sh21, sh22);
}

// round 8
// speedup vs baseline: 3.1108x; 1.0685x over previous
#include <cuda_runtime.h>
#include <cstdint>

#define BATCH 32
#define CH    256
#define HH    56
#define WW    56
#define HW    (HH*WW)              // 3136
#define NPIX  (BATCH*HW)           // 100352
#define NELEM (BATCH*CH*HW)
#define NWORD 8
#define KTAPS 9
#define EPSBN 1e-5f

// -------------------- device scratch --------------------
__device__ __align__(16) float    g_y[NELEM];
__device__ __align__(16) uint32_t g_abits1[NPIX*NWORD];        // pack(in + shA) bits, [pix][8]
__device__ __align__(16) uint32_t g_ebits [NPIX*NWORD];        // e = a1^a2 bits,    [pix][8]
__device__ unsigned short g_pe[NPIX];                          // popc of 8 e-words per pixel
__device__ uint8_t        g_emask[NPIX];                       // 8-bit mask: which e-words nonzero
__device__ __align__(16) uint32_t g_wcol[2][KTAPS*NWORD*CH];   // [blk][(tap*8+wd)*256 + o]
__device__ int   g_popcw[2][KTAPS*CH];                         // [blk][tap*256 + o]
__device__ float g_k1[2][CH], g_k2[2][CH], g_c0[2][CH];

// -------------------- prep --------------------
__global__ void prep_kernel(const float* __restrict__ wA, const float* __restrict__ scA,
                            const float* __restrict__ gA, const float* __restrict__ betaA,
                            const float* __restrict__ meanA, const float* __restrict__ varA,
                            const float* __restrict__ wB, const float* __restrict__ scB,
                            const float* __restrict__ gB, const float* __restrict__ betaB,
                            const float* __restrict__ meanB, const float* __restrict__ varB)
{
    const int blk = blockIdx.y;
    const float* w    = blk ? wB : wA;
    const float* sc   = blk ? scB : scA;
    const float* g    = blk ? gB : gA;
    const float* beta = blk ? betaB : betaA;
    const float* mean = blk ? meanB : meanA;
    const float* var  = blk ? varB : varA;

    const int o = blockIdx.x, tid = threadIdx.x;   // 128 threads
    __shared__ float red[128];
    __shared__ int   tapc[KTAPS];

    float s = 0.f;
    const float* wo = w + o * (CH * KTAPS);
    for (int i = tid; i < CH * KTAPS; i += 128) s += fabsf(wo[i]);
    red[tid] = s;
    __syncthreads();
    for (int st = 64; st > 0; st >>= 1) {
        if (tid < st) red[tid] += red[tid + st];
        __syncthreads();
    }
    if (tid < KTAPS) tapc[tid] = 0;
    __syncthreads();

    if (tid < KTAPS * NWORD) {
        const int tap = tid / NWORD;
        const int wd  = tid % NWORD;
        uint32_t bits = 0;
        #pragma unroll
        for (int j = 0; j < 32; j++) {
            const int c = wd * 32 + j;
            const float wv = w[(o * CH + c) * KTAPS + tap];
            bits |= (uint32_t)(wv > 0.f) << j;
        }
        g_wcol[blk][(tap * NWORD + wd) * CH + o] = bits;
        atomicAdd(&tapc[tap], __popc(bits));
    }
    __syncthreads();
    if (tid < KTAPS) g_popcw[blk][tid * CH + o] = tapc[tid];

    if (tid == 0) {
        const float alpha = red[0] / (float)(CH * KTAPS);
        const float istd  = rsqrtf(var[o] + EPSBN);
        const float k1 = alpha * istd * g[o];
        g_k1[blk][o] = k1;
        g_k2[blk][o] = sc[o] * k1;
        g_c0[blk][o] = beta[o] - mean[o] * istd * g[o];
    }
}

// -------------------- pack: float NCHW -> a1 bits + e bits + pe + emask --------------------
__global__ void pack_kernel(const float* __restrict__ in,
                            const float* __restrict__ shA, const float* __restrict__ shB)
{
    __shared__ float s1[CH], s2[CH];
    const int tid = threadIdx.x;
    s1[tid] = shA[tid]; s2[tid] = shB[tid];
    __syncthreads();

    const int pix = blockIdx.x * blockDim.x + tid;
    if (pix >= NPIX) return;
    const int b  = pix / HW;
    const int hw = pix % HW;
    const int base = b * (CH * HW) + hw;

    int pe = 0;
    int mask = 0;
    #pragma unroll
    for (int k = 0; k < NWORD; k++) {
        uint32_t b1 = 0, b2 = 0;
        #pragma unroll
        for (int j = 0; j < 32; j++) {
            const int c = k * 32 + j;
            const float v = in[base + c * HW];
            b1 |= (uint32_t)(v + s1[c] > 0.f) << j;
            b2 |= (uint32_t)(v + s2[c] > 0.f) << j;
        }
        const uint32_t e = b1 ^ b2;
        g_abits1[pix * NWORD + k] = b1;
        g_ebits [pix * NWORD + k] = e;
        pe += __popc(e);
        mask |= (e != 0u) << k;
    }
    g_pe[pix]    = (unsigned short)pe;
    g_emask[pix] = (uint8_t)mask;
}

// -------------------- CSA popcount --------------------
__device__ __forceinline__ void fa3(uint32_t a, uint32_t b, uint32_t c,
                                    uint32_t& s, uint32_t& cy) {
    s  = a ^ b ^ c;
    cy = (a & b) | (c & (a ^ b));
}

__device__ __forceinline__ int csa_popc8(uint32_t x0, uint32_t x1, uint32_t x2, uint32_t x3,
                                         uint32_t x4, uint32_t x5, uint32_t x6, uint32_t x7) {
    uint32_t s1a, c2a, s1b, c2b, s1c, c2c, s2, c4;
    fa3(x0, x1, x2, s1a, c2a);
    fa3(x3, x4, x5, s1b, c2b);
    fa3(s1a, s1b, x6, s1c, c2c);
    fa3(c2a, c2b, c2c, s2, c4);
    return __popc(s1c) + __popc(x7) + 2 * __popc(s2) + 4 * __popc(c4);
}

// -------------------- conv: o-lane XNOR with e-sparsified second activation --------------------
// CTA: 256 thr = 8 warps. Covers ONE output row, 28 px, 128 o (o-half by blockIdx.z).
//   warps 0-3: o 0-127, px 0-13;  warps 4-7: o 0-127, px 14-27.
// smem: wsm 9216 words (36.9KB, reused as stage in epilogue) + a1/e tiles + pe/emask.
#define SM_W     9216                 // (tap*8+wd)*128 + olocal
#define SM_A1    (SM_W)               // +720: [r*30+c]*8 + wd
#define SM_E     (SM_W + 720)
#define SM_PE    (SM_W + 1440)       // 45 u32 = 90 u16
#define SM_EM    (SM_W + 1485)       // 23 u32 = 90 u8 (padded)
#define SM_TOT   (SM_W + 1512)       // 42912 B

__global__ __launch_bounds__(256, 4)
void conv_kernel(int blk, const float* __restrict__ res, float* __restrict__ out)
{
    __shared__ __align__(16) uint32_t sm[SM_TOT];

    const int tid  = threadIdx.x;
    const int warp = tid >> 5, lane = tid & 31;
    const int h     = blockIdx.x >> 1;
    const int wseg  = blockIdx.x & 1;
    const int b     = blockIdx.y;
    const int ohalf = blockIdx.z;
    const int w0    = wseg * 28;
    const int olocal = (warp & 3) * 32 + lane;     // 0..127
    const int o      = ohalf * 128 + olocal;
    const int pxgrp  = warp >> 2;                  // 0 or 1

    // ---- stage w-half into smem: dest (tap*8+wd)*128 + j, src (tap*8+wd)*256 + ohalf*128 + j ----
    {
        const uint4* src4 = reinterpret_cast<const uint4*>(g_wcol[blk]);
        uint4* dst4 = reinterpret_cast<uint4*>(sm);
        #pragma unroll
        for (int it = 0; it < 9; it++) {
            const int idx = it * 256 + tid;        // 0..2303 uint4
            const int tw = idx >> 5;               // tap*8+wd
            const int j  = idx & 31;
            dst4[idx] = src4[tw * 64 + ohalf * 32 + j];
        }
    }
    // ---- act tile: 3 rows x 30 cols (a1 + e), plus pe/emask ----
    {
        const uint4* a1g = reinterpret_cast<const uint4*>(g_abits1);
        const uint4* eg  = reinterpret_cast<const uint4*>(g_ebits);
        uint4* a1d = reinterpret_cast<uint4*>(sm + SM_A1);
        uint4* ed  = reinterpret_cast<uint4*>(sm + SM_E);
        unsigned short* ped = reinterpret_cast<unsigned short*>(sm + SM_PE);
        uint8_t* emd = reinterpret_cast<uint8_t*>(sm + SM_EM);
        for (int idx = tid; idx < 360; idx += 256) {
            const int arr  = idx / 180;
            const int cell = (idx % 180) >> 1;
            const int half = idx & 1;
            const int r = cell / 30, c = cell % 30;
            const int gh = h - 1 + r, gc = w0 - 1 + c;
            uint4 v = make_uint4(0u, 0u, 0u, 0u);
            if (gh >= 0 && gh < HH && gc >= 0 && gc < WW) {
                const int pix = (b * HH + gh) * WW + gc;
                v = (arr == 0 ? a1g : eg)[pix * 2 + half];
            }
            (arr == 0 ? a1d : ed)[cell * 2 + half] = v;
        }
        for (int idx = tid; idx < 90; idx += 256) {
            const int r = idx / 30, c = idx % 30;
            const int gh = h - 1 + r, gc = w0 - 1 + c;
            unsigned short pv = 0; uint8_t mv = 0;
            if (gh >= 0 && gh < HH && gc >= 0 && gc < WW) {
                const int pix = (b * HH + gh) * WW + gc;
                pv = g_pe[pix]; mv = g_emask[pix];
            }
            ped[idx] = pv; emd[idx] = mv;
        }
    }
    __syncthreads();

    const float k1 = __ldg(&g_k1[blk][o]);
    const float k2 = __ldg(&g_k2[blk][o]);
    const float c0 = __ldg(&g_c0[blk][o]);
    const uint8_t* emd = reinterpret_cast<const uint8_t*>(sm + SM_EM);
    const uint4*   a1sm4 = reinterpret_cast<const uint4*>(sm + SM_A1);

    int acc[14];
    #pragma unroll
    for (int i = 0; i < 14; i++) acc[i] = 0;

    #pragma unroll
    for (int tg = 0; tg < 3; tg++) {           // tap row; act tile row r = tg
        uint32_t wr[24];
        #pragma unroll
        for (int i = 0; i < 24; i++)
            wr[i] = sm[((tg * 3 + i / 8) * 8 + (i & 7)) * 128 + olocal];

        #pragma unroll
        for (int pi = 0; pi < 14; pi++) {
            const int px = pxgrp * 14 + pi;
            int p1 = 0, dlt = 0;
            #pragma unroll
            for (int t3 = 0; t3 < 3; t3++) {
                const int cell = tg * 30 + px + t3;
                const uint4 A0 = a1sm4[cell * 2];
                const uint4 A1 = a1sm4[cell * 2 + 1];
                p1 += csa_popc8(A0.x ^ wr[t3*8+0], A0.y ^ wr[t3*8+1],
                                A0.z ^ wr[t3*8+2], A0.w ^ wr[t3*8+3],
                                A1.x ^ wr[t3*8+4], A1.y ^ wr[t3*8+5],
                                A1.z ^ wr[t3*8+6], A1.w ^ wr[t3*8+7]);
                int m = emd[cell];
                while (m) {                    // warp-uniform sparse act2 correction
                    const int idx = __ffs(m) - 1;
                    m &= m - 1;
                    const uint32_t e = sm[SM_E  + cell * 8 + idx];
                    const uint32_t a = sm[SM_A1 + cell * 8 + idx];
                    const uint32_t w = sm[((tg * 3 + t3) * 8 + idx) * 128 + olocal];
                    dlt += __popc((a ^ w) & e);
                }
            }
            acc[pi] += p1 + (dlt << 16);       // p1<=2304, dlt<=2304: no overflow over 3 tg
        }
    }

    __syncthreads();                           // all reads of wsm done -> reuse as stage
    float* stg = reinterpret_cast<float*>(sm); // [128 o][29]
    const unsigned short* ped = reinterpret_cast<const unsigned short*>(sm + SM_PE);
    const int* pcw = g_popcw[blk];

    #pragma unroll
    for (int pi = 0; pi < 14; pi++) {
        const int px = pxgrp * 14 + pi;
        int E = 0;
        #pragma unroll
        for (int dr = 0; dr < 3; dr++)
            #pragma unroll
            for (int dc = 0; dc < 3; dc++) E += ped[dr * 30 + px + dc];

        int corr = 0;
        {
            int mask9 = 0;
            if (h == 0)            mask9 |= 0x007;
            if (h == HH - 1)       mask9 |= 0x1C0;
            if (w0 + px == 0)      mask9 |= 0x049;
            if (w0 + px == WW - 1) mask9 |= 0x124;
            if (mask9) {
                #pragma unroll
                for (int tap = 0; tap < 9; tap++)
                    if ((mask9 >> tap) & 1)
                        corr += CH - 2 * __ldg(&pcw[tap * CH + o]);
            }
        }
        const int p1  = acc[pi] & 0xFFFF;
        const int dlt = acc[pi] >> 16;
        const int d1 = CH * KTAPS - 2 * p1 - corr;
        const int d2 = d1 - 2 * E + 4 * dlt;
        stg[olocal * 29 + px] = k1 * (float)d1 + k2 * (float)d2 + c0;
    }
    __syncthreads();

    // coalesced residual+clamp+store: 128 o x 28 px
    #pragma unroll
    for (int it = 0; it < 14; it++) {
        const int id = it * 256 + tid;
        const int oL = id / 28, px = id % 28;
        const int og = ohalf * 128 + oL;
        const int gidx = (b * CH + og) * HW + h * WW + (w0 + px);
        float v = stg[oL * 29 + px] + res[gidx];
        out[gidx] = fminf(fmaxf(v, -1.0f), 1.0f);
    }
}

// -------------------- launch --------------------
extern "C" void kernel_launch(void* const* d_in, const int* in_sizes, int n_in,
                              void* d_out, int out_size)
{
    const float* x    = (const float*)d_in[0];
    const float* sh11 = (const float*)d_in[1];
    const float* sh12 = (const float*)d_in[2];
    const float* w1   = (const float*)d_in[3];
    const float* sc1  = (const float*)d_in[4];
    const float* g1   = (const float*)d_in[5];
    const float* b1   = (const float*)d_in[6];
    const float* m1   = (const float*)d_in[7];
    const float* v1   = (const float*)d_in[8];
    const float* sh21 = (const float*)d_in[9];
    const float* sh22 = (const float*)d_in[10];
    const float* w2   = (const float*)d_in[11];
    const float* sc2  = (const float*)d_in[12];
    const float* g2   = (const float*)d_in[13];
    const float* b2   = (const float*)d_in[14];
    const float* m2   = (const float*)d_in[15];
    const float* v2   = (const float*)d_in[16];
    float* outp = (float*)d_out;

    void* yp_raw = nullptr;
    cudaGetSymbolAddress(&yp_raw, g_y);
    float* yp = (float*)yp_raw;

    dim3 pgrid(CH, 2);
    prep_kernel<<<pgrid, 128>>>(w1, sc1, g1, b1, m1, v1,
                                w2, sc2, g2, b2, m2, v2);

    dim3 cgrid(112, BATCH, 2);   // (2 wseg x 56 h), batch, o-half

    pack_kernel<<<(NPIX + 255) / 256, 256>>>(x, sh11, sh12);
    conv_kernel<<<cgrid, 256>>>(0, x, yp);

    pack_kernel<<<(NPIX + 255) / 256, 256>>>(yp, sh21, sh22);
    conv_kernel<<<cgrid, 256>>>(1, yp, outp);
}

// round 9
// speedup vs baseline: 4.6208x; 1.4854x over previous
#include <cuda_runtime.h>
#include <cstdint>

#define BATCH 32
#define CH    256
#define HH    56
#define WW    56
#define HW    (HH*WW)              // 3136
#define NPIX  (BATCH*HW)           // 100352
#define NELEM (BATCH*CH*HW)
#define NWORD 8
#define KTAPS 9
#define EPSBN 1e-5f

// -------------------- device scratch --------------------
__device__ __align__(16) float    g_y[NELEM];
__device__ __align__(16) uint32_t g_abits1[NPIX*NWORD];        // pack(in + shA) bits, [pix][8]
__device__ __align__(16) uint32_t g_ebits [NPIX*NWORD];        // e = a1^a2 bits,    [pix][8]
__device__ unsigned short g_pe[NPIX];                          // popc of 8 e-words per pixel
__device__ uint8_t        g_emask[NPIX];                       // which e-words nonzero
__device__ __align__(16) uint32_t g_wcol[2][KTAPS*NWORD*CH];   // [blk][(tap*8+wd)*256 + o]
__device__ int   g_popcw[2][KTAPS*CH];                         // [blk][tap*256 + o]
__device__ float g_k1[2][CH], g_k2[2][CH], g_c0[2][CH];

// -------------------- prep --------------------
__global__ void prep_kernel(const float* __restrict__ wA, const float* __restrict__ scA,
                            const float* __restrict__ gA, const float* __restrict__ betaA,
                            const float* __restrict__ meanA, const float* __restrict__ varA,
                            const float* __restrict__ wB, const float* __restrict__ scB,
                            const float* __restrict__ gB, const float* __restrict__ betaB,
                            const float* __restrict__ meanB, const float* __restrict__ varB)
{
    const int blk = blockIdx.y;
    const float* w    = blk ? wB : wA;
    const float* sc   = blk ? scB : scA;
    const float* g    = blk ? gB : gA;
    const float* beta = blk ? betaB : betaA;
    const float* mean = blk ? meanB : meanA;
    const float* var  = blk ? varB : varA;

    const int o = blockIdx.x, tid = threadIdx.x;   // 128 threads
    __shared__ float red[128];
    __shared__ int   tapc[KTAPS];

    float s = 0.f;
    const float* wo = w + o * (CH * KTAPS);
    for (int i = tid; i < CH * KTAPS; i += 128) s += fabsf(wo[i]);
    red[tid] = s;
    __syncthreads();
    for (int st = 64; st > 0; st >>= 1) {
        if (tid < st) red[tid] += red[tid + st];
        __syncthreads();
    }
    if (tid < KTAPS) tapc[tid] = 0;
    __syncthreads();

    if (tid < KTAPS * NWORD) {
        const int tap = tid / NWORD;
        const int wd  = tid % NWORD;
        uint32_t bits = 0;
        #pragma unroll
        for (int j = 0; j < 32; j++) {
            const int c = wd * 32 + j;
            const float wv = w[(o * CH + c) * KTAPS + tap];
            bits |= (uint32_t)(wv > 0.f) << j;
        }
        g_wcol[blk][(tap * NWORD + wd) * CH + o] = bits;
        atomicAdd(&tapc[tap], __popc(bits));
    }
    __syncthreads();
    if (tid < KTAPS) g_popcw[blk][tid * CH + o] = tapc[tid];

    if (tid == 0) {
        const float alpha = red[0] / (float)(CH * KTAPS);
        const float istd  = rsqrtf(var[o] + EPSBN);
        const float k1 = alpha * istd * g[o];
        g_k1[blk][o] = k1;
        g_k2[blk][o] = sc[o] * k1;
        g_c0[blk][o] = beta[o] - mean[o] * istd * g[o];
    }
}

// -------------------- pack --------------------
__global__ void pack_kernel(const float* __restrict__ in,
                            const float* __restrict__ shA, const float* __restrict__ shB)
{
    __shared__ float s1[CH], s2[CH];
    const int tid = threadIdx.x;
    s1[tid] = shA[tid]; s2[tid] = shB[tid];
    __syncthreads();

    const int pix = blockIdx.x * blockDim.x + tid;
    if (pix >= NPIX) return;
    const int b  = pix / HW;
    const int hw = pix % HW;
    const int base = b * (CH * HW) + hw;

    int pe = 0;
    int mask = 0;
    #pragma unroll
    for (int k = 0; k < NWORD; k++) {
        uint32_t b1 = 0, b2 = 0;
        #pragma unroll
        for (int j = 0; j < 32; j++) {
            const int c = k * 32 + j;
            const float v = in[base + c * HW];
            b1 |= (uint32_t)(v + s1[c] > 0.f) << j;
            b2 |= (uint32_t)(v + s2[c] > 0.f) << j;
        }
        const uint32_t e = b1 ^ b2;
        g_abits1[pix * NWORD + k] = b1;
        g_ebits [pix * NWORD + k] = e;
        pe += __popc(e);
        mask |= (e != 0u) << k;
    }
    g_pe[pix]    = (unsigned short)pe;
    g_emask[pix] = (uint8_t)mask;
}

// -------------------- CSA popcount --------------------
__device__ __forceinline__ void fa3(uint32_t a, uint32_t b, uint32_t c,
                                    uint32_t& s, uint32_t& cy) {
    s  = a ^ b ^ c;
    cy = (a & b) | (c & (a ^ b));
}

__device__ __forceinline__ int csa_popc8(uint32_t x0, uint32_t x1, uint32_t x2, uint32_t x3,
                                         uint32_t x4, uint32_t x5, uint32_t x6, uint32_t x7) {
    uint32_t s1a, c2a, s1b, c2b, s1c, c2c, s2, c4;
    fa3(x0, x1, x2, s1a, c2a);
    fa3(x3, x4, x5, s1b, c2b);
    fa3(s1a, s1b, x6, s1c, c2c);
    fa3(c2a, c2b, c2c, s2, c4);
    return __popc(s1c) + __popc(x7) + 2 * __popc(s2) + 4 * __popc(c4);
}

// -------------------- conv: cell-centric o-lane XNOR + e-sparse act2 --------------------
#define SM_W     9216                 // (tap*8+wd)*128 + olocal
#define SM_A1    (SM_W)               // +720: [cell]*8 + wd  (cell = r*30+c, 90 cells)
#define SM_E     (SM_W + 720)
#define SM_PE    (SM_W + 1440)        // 90 u16
#define SM_EM    (SM_W + 1485)        // 90 u8
#define SM_TOT   (SM_W + 1512)

__global__ __launch_bounds__(256, 4)
void conv_kernel(int blk, const float* __restrict__ res, float* __restrict__ out)
{
    __shared__ __align__(16) uint32_t sm[SM_TOT];

    const int tid  = threadIdx.x;
    const int warp = tid >> 5, lane = tid & 31;
    const int h     = blockIdx.x >> 1;
    const int wseg  = blockIdx.x & 1;
    const int b     = blockIdx.y;
    const int ohalf = blockIdx.z;
    const int w0    = wseg * 28;
    const int olocal = (warp & 3) * 32 + lane;     // 0..127
    const int o      = ohalf * 128 + olocal;
    const int pxgrp  = warp >> 2;                  // 0 or 1

    // ---- stage w-half ----
    {
        const uint4* src4 = reinterpret_cast<const uint4*>(g_wcol[blk]);
        uint4* dst4 = reinterpret_cast<uint4*>(sm);
        #pragma unroll
        for (int it = 0; it < 9; it++) {
            const int idx = it * 256 + tid;        // 0..2303 uint4
            const int tw = idx >> 5;
            const int j  = idx & 31;
            dst4[idx] = src4[tw * 64 + ohalf * 32 + j];
        }
    }
    // ---- act tiles ----
    {
        const uint4* a1g = reinterpret_cast<const uint4*>(g_abits1);
        const uint4* eg  = reinterpret_cast<const uint4*>(g_ebits);
        uint4* a1d = reinterpret_cast<uint4*>(sm + SM_A1);
        uint4* ed  = reinterpret_cast<uint4*>(sm + SM_E);
        unsigned short* ped = reinterpret_cast<unsigned short*>(sm + SM_PE);
        uint8_t* emd = reinterpret_cast<uint8_t*>(sm + SM_EM);
        for (int idx = tid; idx < 360; idx += 256) {
            const int arr  = idx / 180;
            const int cell = (idx % 180) >> 1;
            const int half = idx & 1;
            const int r = cell / 30, c = cell % 30;
            const int gh = h - 1 + r, gc = w0 - 1 + c;
            uint4 v = make_uint4(0u, 0u, 0u, 0u);
            if (gh >= 0 && gh < HH && gc >= 0 && gc < WW) {
                const int pix = (b * HH + gh) * WW + gc;
                v = (arr == 0 ? a1g : eg)[pix * 2 + half];
            }
            (arr == 0 ? a1d : ed)[cell * 2 + half] = v;
        }
        for (int idx = tid; idx < 90; idx += 256) {
            const int r = idx / 30, c = idx % 30;
            const int gh = h - 1 + r, gc = w0 - 1 + c;
            unsigned short pv = 0; uint8_t mv = 0;
            if (gh >= 0 && gh < HH && gc >= 0 && gc < WW) {
                const int pix = (b * HH + gh) * WW + gc;
                pv = g_pe[pix]; mv = g_emask[pix];
            }
            ped[idx] = pv; emd[idx] = mv;
        }
    }
    __syncthreads();

    const float k1 = __ldg(&g_k1[blk][o]);
    const float k2 = __ldg(&g_k2[blk][o]);
    const float c0 = __ldg(&g_c0[blk][o]);
    const uint8_t* emd = reinterpret_cast<const uint8_t*>(sm + SM_EM);
    const uint4*   a1sm4 = reinterpret_cast<const uint4*>(sm + SM_A1);

    int acc[14];                                   // p1 low 16, delta high 16
    #pragma unroll
    for (int i = 0; i < 14; i++) acc[i] = 0;

    #pragma unroll 1
    for (int tg = 0; tg < 3; tg++) {               // tap row (rolled: bounds I$)
        uint32_t wr[24];
        #pragma unroll
        for (int i = 0; i < 24; i++)
            wr[i] = sm[((tg * 3 + i / 8) * 8 + (i & 7)) * 128 + olocal];
        const int cbase = tg * 30 + pxgrp * 14;
        const uint32_t wbase = (uint32_t)(tg * 3) * 8 * 128 + (uint32_t)olocal;

        #pragma unroll
        for (int cc = 0; cc < 16; cc++) {          // cell-centric: each cell read ONCE
            const int cell = cbase + cc;
            const uint4 A0 = a1sm4[cell * 2];
            const uint4 A1 = a1sm4[cell * 2 + 1];
            #pragma unroll
            for (int t3 = 0; t3 < 3; t3++) {
                const int pi = cc - t3;
                if (pi >= 0 && pi < 14) {
                    acc[pi] += csa_popc8(
                        A0.x ^ wr[t3*8+0], A0.y ^ wr[t3*8+1],
                        A0.z ^ wr[t3*8+2], A0.w ^ wr[t3*8+3],
                        A1.x ^ wr[t3*8+4], A1.y ^ wr[t3*8+5],
                        A1.z ^ wr[t3*8+6], A1.w ^ wr[t3*8+7]);
                }
            }
            int m = emd[cell];                     // warp-uniform
            while (m) {
                const int idx = __ffs(m) - 1;
                m &= m - 1;
                const uint32_t e = sm[SM_E  + cell * 8 + idx];
                const uint32_t a = sm[SM_A1 + cell * 8 + idx];
                const uint32_t ax = a ^ e;         // reused across taps? no: fold a^w per tap
                (void)ax;
                #pragma unroll
                for (int t3 = 0; t3 < 3; t3++) {
                    const int pi = cc - t3;
                    if (pi >= 0 && pi < 14) {
                        const uint32_t w = sm[wbase + (uint32_t)(t3 * 8 + idx) * 128];
                        acc[pi] += __popc((a ^ w) & e) << 16;
                    }
                }
            }
        }
    }

    __syncthreads();                               // wsm reads done -> reuse as stage
    float* stg = reinterpret_cast<float*>(sm);     // [128 o][29]
    const unsigned short* ped = reinterpret_cast<const unsigned short*>(sm + SM_PE);
    const int* pcw = g_popcw[blk];

    #pragma unroll
    for (int pi = 0; pi < 14; pi++) {
        const int px = pxgrp * 14 + pi;
        int E = 0;
        #pragma unroll
        for (int dr = 0; dr < 3; dr++)
            #pragma unroll
            for (int dc = 0; dc < 3; dc++) E += ped[dr * 30 + px + dc];

        int corr = 0;
        {
            int mask9 = 0;
            if (h == 0)            mask9 |= 0x007;
            if (h == HH - 1)       mask9 |= 0x1C0;
            if (w0 + px == 0)      mask9 |= 0x049;
            if (w0 + px == WW - 1) mask9 |= 0x124;
            if (mask9) {
                #pragma unroll
                for (int tap = 0; tap < 9; tap++)
                    if ((mask9 >> tap) & 1)
                        corr += CH - 2 * __ldg(&pcw[tap * CH + o]);
            }
        }
        const int p1  = acc[pi] & 0xFFFF;
        const int dlt = acc[pi] >> 16;
        const int d1 = CH * KTAPS - 2 * p1 - corr;
        const int d2 = d1 - 2 * E + 4 * dlt;
        stg[olocal * 29 + px] = k1 * (float)d1 + k2 * (float)d2 + c0;
    }
    __syncthreads();

    #pragma unroll
    for (int it = 0; it < 14; it++) {
        const int id = it * 256 + tid;
        const int oL = id / 28, px = id % 28;
        const int og = ohalf * 128 + oL;
        const int gidx = (b * CH + og) * HW + h * WW + (w0 + px);
        float v = stg[oL * 29 + px] + res[gidx];
        out[gidx] = fminf(fmaxf(v, -1.0f), 1.0f);
    }
}

// -------------------- launch --------------------
extern "C" void kernel_launch(void* const* d_in, const int* in_sizes, int n_in,
                              void* d_out, int out_size)
{
    const float* x    = (const float*)d_in[0];
    const float* sh11 = (const float*)d_in[1];
    const float* sh12 = (const float*)d_in[2];
    const float* w1   = (const float*)d_in[3];
    const float* sc1  = (const float*)d_in[4];
    const float* g1   = (const float*)d_in[5];
    const float* b1   = (const float*)d_in[6];
    const float* m1   = (const float*)d_in[7];
    const float* v1   = (const float*)d_in[8];
    const float* sh21 = (const float*)d_in[9];
    const float* sh22 = (const float*)d_in[10];
    const float* w2   = (const float*)d_in[11];
    const float* sc2  = (const float*)d_in[12];
    const float* g2   = (const float*)d_in[13];
    const float* b2   = (const float*)d_in[14];
    const float* m2   = (const float*)d_in[15];
    const float* v2   = (const float*)d_in[16];
    float* outp = (float*)d_out;

    void* yp_raw = nullptr;
    cudaGetSymbolAddress(&yp_raw, g_y);
    float* yp = (float*)yp_raw;

    dim3 pgrid(CH, 2);
    prep_kernel<<<pgrid, 128>>>(w1, sc1, g1, b1, m1, v1,
                                w2, sc2, g2, b2, m2, v2);

    dim3 cgrid(112, BATCH, 2);

    pack_kernel<<<(NPIX + 255) / 256, 256>>>(x, sh11, sh12);
    conv_kernel<<<cgrid, 256>>>(0, x, yp);

    pack_kernel<<<(NPIX + 255) / 256, 256>>>(yp, sh21, sh22);
    conv_kernel<<<cgrid, 256>>>(1, yp, outp);
}